// round 16
// baseline (speedup 1.0000x reference)
#include <cuda_runtime.h>
#include <float.h>
#include <stdint.h>

// SparseSoftmax: masked softmax over last axis of (32, 2048, 2048) fp32
// with int32 mask (mask = OD != 0). Fully-masked rows -> zeros.
//
// FINAL CONVERGED KERNEL (best measured: dur 227.84 us / kernel 219.4 us,
// DRAM 89.8%, 7.12 TB/s = GB300 LTS crossbar cap on 1.61 GB one-touch traffic):
//   - one CTA of 128 threads per row, 16 elements/thread
//   - Blackwell 256-bit vector ops: 2x ld.global.nc.v8.f32 (features) +
//     2x ld.global.nc.v8.b32 (mask) + 2x st.global.cs.v8.f32 (output,
//     evict-first: the output stream is dead after write)
//   - v8 ops keep regs at 32 -> 96% occupancy WITH 8-request/warp MLP;
//     the unique sweep point combining both:
//       MLP2/occ91: 256.7us | MLP4/occ95: 220.9 | MLP8-v4/occ72: 221.1
//       MLP8-v8/occ96: 219.4 (this) | MLP16-v8/occ47: 221.2
//   - mask folded to -inf at load time (exp gives exact 0 on masked lanes)

#define ROW_LEN 2048
#define THREADS 128
#define EPT     16
#define NWARPS  (THREADS / 32)   // 4

__device__ __forceinline__ void ldg256_f32(float* r, const float* p) {
    asm volatile(
        "ld.global.nc.v8.f32 {%0,%1,%2,%3,%4,%5,%6,%7}, [%8];"
        : "=f"(r[0]), "=f"(r[1]), "=f"(r[2]), "=f"(r[3]),
          "=f"(r[4]), "=f"(r[5]), "=f"(r[6]), "=f"(r[7])
        : "l"(p));
}

__device__ __forceinline__ void ldg256_s32(int* r, const int* p) {
    asm volatile(
        "ld.global.nc.v8.b32 {%0,%1,%2,%3,%4,%5,%6,%7}, [%8];"
        : "=r"(r[0]), "=r"(r[1]), "=r"(r[2]), "=r"(r[3]),
          "=r"(r[4]), "=r"(r[5]), "=r"(r[6]), "=r"(r[7])
        : "l"(p));
}

__device__ __forceinline__ void stg256_cs_f32(float* p, const float* r) {
    asm volatile(
        "st.global.cs.v8.f32 [%0], {%1,%2,%3,%4,%5,%6,%7,%8};"
        :: "l"(p),
           "f"(r[0]), "f"(r[1]), "f"(r[2]), "f"(r[3]),
           "f"(r[4]), "f"(r[5]), "f"(r[6]), "f"(r[7])
        : "memory");
}

__global__ __launch_bounds__(THREADS)
void sparse_softmax_kernel(const float* __restrict__ f,
                           const int* __restrict__ od,
                           float* __restrict__ out)
{
    const int row = blockIdx.x;
    const size_t base = (size_t)row * ROW_LEN;

    const int t    = threadIdx.x;
    const int warp = t >> 5;
    const int lane = t & 31;
    const float NEG_INF = __int_as_float(0xff800000);

    // Two 256-bit feature loads + two 256-bit mask loads per thread.
    // Thread t covers elements [t*8, t*8+8) and [1024 + t*8, 1024 + t*8+8).
    const float* fp0 = f  + base + (size_t)t * 8;
    const float* fp1 = fp0 + ROW_LEN / 2;
    const int*   mp0 = od + base + (size_t)t * 8;
    const int*   mp1 = mp0 + ROW_LEN / 2;

    float vals[EPT];
    int   msk [EPT];
    ldg256_f32(vals,     fp0);
    ldg256_f32(vals + 8, fp1);
    ldg256_s32(msk,      mp0);
    ldg256_s32(msk + 8,  mp1);

    // Fold mask into values: masked-out lanes become -inf.
    #pragma unroll
    for (int i = 0; i < EPT; i++)
        vals[i] = msk[i] ? vals[i] : NEG_INF;

    __shared__ float smax[NWARPS];
    __shared__ float ssum[NWARPS];

    // --- max reduce (masked lanes are -inf, harmless) ---
    float mx = NEG_INF;
    #pragma unroll
    for (int i = 0; i < EPT; i++) mx = fmaxf(mx, vals[i]);
    #pragma unroll
    for (int o = 16; o > 0; o >>= 1)
        mx = fmaxf(mx, __shfl_xor_sync(0xffffffffu, mx, o));
    if (lane == 0) smax[warp] = mx;
    __syncthreads();

    float rowmax = smax[0];
    #pragma unroll
    for (int w = 1; w < NWARPS; w++) rowmax = fmaxf(rowmax, smax[w]);
    // Fully-masked row: rowmax = -inf would give NaN in (v - rowmax); clamp.
    if (!(rowmax > NEG_INF)) rowmax = 0.0f;

    // --- exp + sum; exp(-inf - rowmax) = 0 on masked lanes ---
    float sum = 0.0f;
    #pragma unroll
    for (int i = 0; i < EPT; i++) {
        vals[i] = __expf(vals[i] - rowmax);   // overwrite in place: p[i]
        sum += vals[i];
    }
    #pragma unroll
    for (int o = 16; o > 0; o >>= 1)
        sum += __shfl_xor_sync(0xffffffffu, sum, o);
    if (lane == 0) ssum[warp] = sum;
    __syncthreads();

    float s = ssum[0];
    #pragma unroll
    for (int w = 1; w < NWARPS; w++) s += ssum[w];
    const float inv = (s > 0.0f) ? (1.0f / s) : 0.0f;   // fully-masked -> zeros

    // --- normalize + two evict-first 256-bit stores ---
    #pragma unroll
    for (int i = 0; i < EPT; i++) vals[i] *= inv;

    float* op0 = out + base + (size_t)t * 8;
    float* op1 = op0 + ROW_LEN / 2;
    stg256_cs_f32(op0, vals);
    stg256_cs_f32(op1, vals + 8);
}

extern "C" void kernel_launch(void* const* d_in, const int* in_sizes, int n_in,
                              void* d_out, int out_size)
{
    const float* features = (const float*)d_in[0];
    const int*   OD       = (const int*)d_in[1];
    float*       out      = (float*)d_out;

    const int rows = in_sizes[0] / ROW_LEN;   // 32*2048 = 65536
    sparse_softmax_kernel<<<rows, THREADS>>>(features, OD, out);
}

// round 17
// speedup vs baseline: 1.0101x; 1.0101x over previous
#include <cuda_runtime.h>
#include <float.h>
#include <stdint.h>

// SparseSoftmax: masked softmax over last axis of (32, 2048, 2048) fp32
// with int32 mask (mask = OD != 0). Fully-masked rows -> zeros.
//
// FINAL CONVERGED KERNEL (best measured: dur 227.84 us / kernel 219.4 us,
// DRAM 89.8%, 7.12 TB/s = GB300 LTS crossbar cap on 1.61 GB one-touch traffic):
//   - one CTA of 128 threads per row, 16 elements/thread
//   - Blackwell 256-bit vector ops: 2x ld.global.nc.v8.f32 (features) +
//     2x ld.global.nc.v8.b32 (mask) + 2x st.global.cs.v8.f32 (output,
//     evict-first: the output stream is dead after write)
//   - v8 ops keep regs at 32 -> 96% occupancy WITH 8-request/warp MLP;
//     the unique sweep point combining both:
//       MLP2/occ91: 256.7us | MLP4/occ95: 220.9 | MLP8-v4/occ72: 221.1
//       MLP8-v8/occ96: 219.4 (this) | MLP16-v8/occ47: 221.2
//   - mask folded to -inf at load time (exp gives exact 0 on masked lanes)

#define ROW_LEN 2048
#define THREADS 128
#define EPT     16
#define NWARPS  (THREADS / 32)   // 4

__device__ __forceinline__ void ldg256_f32(float* r, const float* p) {
    asm volatile(
        "ld.global.nc.v8.f32 {%0,%1,%2,%3,%4,%5,%6,%7}, [%8];"
        : "=f"(r[0]), "=f"(r[1]), "=f"(r[2]), "=f"(r[3]),
          "=f"(r[4]), "=f"(r[5]), "=f"(r[6]), "=f"(r[7])
        : "l"(p));
}

__device__ __forceinline__ void ldg256_s32(int* r, const int* p) {
    asm volatile(
        "ld.global.nc.v8.b32 {%0,%1,%2,%3,%4,%5,%6,%7}, [%8];"
        : "=r"(r[0]), "=r"(r[1]), "=r"(r[2]), "=r"(r[3]),
          "=r"(r[4]), "=r"(r[5]), "=r"(r[6]), "=r"(r[7])
        : "l"(p));
}

__device__ __forceinline__ void stg256_cs_f32(float* p, const float* r) {
    asm volatile(
        "st.global.cs.v8.f32 [%0], {%1,%2,%3,%4,%5,%6,%7,%8};"
        :: "l"(p),
           "f"(r[0]), "f"(r[1]), "f"(r[2]), "f"(r[3]),
           "f"(r[4]), "f"(r[5]), "f"(r[6]), "f"(r[7])
        : "memory");
}

__global__ __launch_bounds__(THREADS)
void sparse_softmax_kernel(const float* __restrict__ f,
                           const int* __restrict__ od,
                           float* __restrict__ out)
{
    const int row = blockIdx.x;
    const size_t base = (size_t)row * ROW_LEN;

    const int t    = threadIdx.x;
    const int warp = t >> 5;
    const int lane = t & 31;
    const float NEG_INF = __int_as_float(0xff800000);

    // Two 256-bit feature loads + two 256-bit mask loads per thread.
    // Thread t covers elements [t*8, t*8+8) and [1024 + t*8, 1024 + t*8+8).
    const float* fp0 = f  + base + (size_t)t * 8;
    const float* fp1 = fp0 + ROW_LEN / 2;
    const int*   mp0 = od + base + (size_t)t * 8;
    const int*   mp1 = mp0 + ROW_LEN / 2;

    float vals[EPT];
    int   msk [EPT];
    ldg256_f32(vals,     fp0);
    ldg256_f32(vals + 8, fp1);
    ldg256_s32(msk,      mp0);
    ldg256_s32(msk + 8,  mp1);

    // Fold mask into values: masked-out lanes become -inf.
    #pragma unroll
    for (int i = 0; i < EPT; i++)
        vals[i] = msk[i] ? vals[i] : NEG_INF;

    __shared__ float smax[NWARPS];
    __shared__ float ssum[NWARPS];

    // --- max reduce (masked lanes are -inf, harmless) ---
    float mx = NEG_INF;
    #pragma unroll
    for (int i = 0; i < EPT; i++) mx = fmaxf(mx, vals[i]);
    #pragma unroll
    for (int o = 16; o > 0; o >>= 1)
        mx = fmaxf(mx, __shfl_xor_sync(0xffffffffu, mx, o));
    if (lane == 0) smax[warp] = mx;
    __syncthreads();

    float rowmax = smax[0];
    #pragma unroll
    for (int w = 1; w < NWARPS; w++) rowmax = fmaxf(rowmax, smax[w]);
    // Fully-masked row: rowmax = -inf would give NaN in (v - rowmax); clamp.
    if (!(rowmax > NEG_INF)) rowmax = 0.0f;

    // --- exp + sum; exp(-inf - rowmax) = 0 on masked lanes ---
    float sum = 0.0f;
    #pragma unroll
    for (int i = 0; i < EPT; i++) {
        vals[i] = __expf(vals[i] - rowmax);   // overwrite in place: p[i]
        sum += vals[i];
    }
    #pragma unroll
    for (int o = 16; o > 0; o >>= 1)
        sum += __shfl_xor_sync(0xffffffffu, sum, o);
    if (lane == 0) ssum[warp] = sum;
    __syncthreads();

    float s = ssum[0];
    #pragma unroll
    for (int w = 1; w < NWARPS; w++) s += ssum[w];
    const float inv = (s > 0.0f) ? (1.0f / s) : 0.0f;   // fully-masked -> zeros

    // --- normalize + two evict-first 256-bit stores ---
    #pragma unroll
    for (int i = 0; i < EPT; i++) vals[i] *= inv;

    float* op0 = out + base + (size_t)t * 8;
    float* op1 = op0 + ROW_LEN / 2;
    stg256_cs_f32(op0, vals);
    stg256_cs_f32(op1, vals + 8);
}

extern "C" void kernel_launch(void* const* d_in, const int* in_sizes, int n_in,
                              void* d_out, int out_size)
{
    const float* features = (const float*)d_in[0];
    const int*   OD       = (const int*)d_in[1];
    float*       out      = (float*)d_out;

    const int rows = in_sizes[0] / ROW_LEN;   // 32*2048 = 65536
    sparse_softmax_kernel<<<rows, THREADS>>>(features, OD, out);
}